// round 1
// baseline (speedup 1.0000x reference)
#include <cuda_runtime.h>
#include <cuda_bf16.h>
#include <math.h>

// Problem constants (fixed by the reference)
#define NE 16          // experts
#define NW 3           // local window
#define NB 64          // batch
#define NP 4096        // patches per expert
#define BP (NB * NP)   // 262144 elements per (expert, projection) plane
#define HBP (BP / 2)   // plane size in float2 units = 131072
#define HP (NP / 2)    // 2048

// scale = sqrt(EXPERT_DIM=128) * |temperature|
// gate[e][w] = (routes[e][w] != e) ? sigmoid(betas[e][w]) : 1.0
// scores[e][w] = Qmean[e] * Kmean[routes[e][w]] / scale * gate[e][w]
// out[b, e*P + p] = softmax_w(scores) . Vmean[routes[e][w]]

__global__ void __launch_bounds__(256)
cantor_attn_kernel(const float2* __restrict__ Qp,
                   const float2* __restrict__ Kp,
                   const float2* __restrict__ Vp,
                   const float*  __restrict__ betas,
                   const float*  __restrict__ temperature,
                   const int*    __restrict__ routes,
                   float2*       __restrict__ out)
{
    __shared__ int   s_route[NE * NW];
    __shared__ float s_gate[NE * NW];
    __shared__ float s_inv;

    const int t = threadIdx.x;
    if (t < NE * NW) {
        int e = t / NW;
        int r = routes[t];
        s_route[t] = r;
        // sigmoid via __expf is plenty accurate for 1e-3 rel err
        s_gate[t] = (r != e) ? (1.0f / (1.0f + __expf(-betas[t]))) : 1.0f;
    }
    if (t == NE * NW) {
        s_inv = 1.0f / (sqrtf(128.0f) * fabsf(temperature[0]));
    }
    __syncthreads();

    // one thread per float2 of the (b,p) plane; grid covers HBP exactly
    const int idx2 = blockIdx.x * blockDim.x + t;   // in [0, HBP)
    const int b   = idx2 / HP;
    const int p2  = idx2 % HP;
    const float inv = s_inv;

    // output float2 base for this (b, p2)
    const long obase = (long)b * (NE * HP) + p2;

    #pragma unroll
    for (int e = 0; e < NE; e++) {
        const int   r0 = s_route[e * NW + 0];
        const int   r1 = s_route[e * NW + 1];
        const int   r2 = s_route[e * NW + 2];
        const float g0 = s_gate[e * NW + 0];
        const float g1 = s_gate[e * NW + 1];
        const float g2 = s_gate[e * NW + 2];

        // Q mean over the 2 projections
        const float2 qa = Qp[(long)(e * 2)     * HBP + idx2];
        const float2 qb = Qp[(long)(e * 2 + 1) * HBP + idx2];

        // neighbor K means
        const float2 k0a = Kp[(long)(r0 * 2)     * HBP + idx2];
        const float2 k0b = Kp[(long)(r0 * 2 + 1) * HBP + idx2];
        const float2 k1a = Kp[(long)(r1 * 2)     * HBP + idx2];
        const float2 k1b = Kp[(long)(r1 * 2 + 1) * HBP + idx2];
        const float2 k2a = Kp[(long)(r2 * 2)     * HBP + idx2];
        const float2 k2b = Kp[(long)(r2 * 2 + 1) * HBP + idx2];

        // neighbor V means
        const float2 v0a = Vp[(long)(r0 * 2)     * HBP + idx2];
        const float2 v0b = Vp[(long)(r0 * 2 + 1) * HBP + idx2];
        const float2 v1a = Vp[(long)(r1 * 2)     * HBP + idx2];
        const float2 v1b = Vp[(long)(r1 * 2 + 1) * HBP + idx2];
        const float2 v2a = Vp[(long)(r2 * 2)     * HBP + idx2];
        const float2 v2b = Vp[(long)(r2 * 2 + 1) * HBP + idx2];

        float2 res;
        {
            // lane .x
            const float q  = 0.5f * (qa.x + qb.x);
            const float k0 = 0.5f * (k0a.x + k0b.x);
            const float k1 = 0.5f * (k1a.x + k1b.x);
            const float k2 = 0.5f * (k2a.x + k2b.x);
            const float v0 = 0.5f * (v0a.x + v0b.x);
            const float v1 = 0.5f * (v1a.x + v1b.x);
            const float v2 = 0.5f * (v2a.x + v2b.x);
            const float qi = q * inv;
            const float s0 = qi * k0 * g0;
            const float s1 = qi * k1 * g1;
            const float s2 = qi * k2 * g2;
            const float m  = fmaxf(fmaxf(s0, s1), s2);
            const float x0 = __expf(s0 - m);
            const float x1 = __expf(s1 - m);
            const float x2 = __expf(s2 - m);
            const float rs = 1.0f / (x0 + x1 + x2);
            res.x = (x0 * v0 + x1 * v1 + x2 * v2) * rs;
        }
        {
            // lane .y
            const float q  = 0.5f * (qa.y + qb.y);
            const float k0 = 0.5f * (k0a.y + k0b.y);
            const float k1 = 0.5f * (k1a.y + k1b.y);
            const float k2 = 0.5f * (k2a.y + k2b.y);
            const float v0 = 0.5f * (v0a.y + v0b.y);
            const float v1 = 0.5f * (v1a.y + v1b.y);
            const float v2 = 0.5f * (v2a.y + v2b.y);
            const float qi = q * inv;
            const float s0 = qi * k0 * g0;
            const float s1 = qi * k1 * g1;
            const float s2 = qi * k2 * g2;
            const float m  = fmaxf(fmaxf(s0, s1), s2);
            const float x0 = __expf(s0 - m);
            const float x1 = __expf(s1 - m);
            const float x2 = __expf(s2 - m);
            const float rs = 1.0f / (x0 + x1 + x2);
            res.y = (x0 * v0 + x1 * v1 + x2 * v2) * rs;
        }

        out[obase + (long)e * HP] = res;
    }
}

extern "C" void kernel_launch(void* const* d_in, const int* in_sizes, int n_in,
                              void* d_out, int out_size)
{
    // metadata order: Q_proj, K_proj, V_proj, betas, temperature, routes, num_patches
    const float2* Qp    = (const float2*)d_in[0];
    const float2* Kp    = (const float2*)d_in[1];
    const float2* Vp    = (const float2*)d_in[2];
    const float*  betas = (const float*)d_in[3];
    const float*  temp  = (const float*)d_in[4];
    const int*    routes= (const int*)d_in[5];
    float2*       out   = (float2*)d_out;

    (void)in_sizes; (void)n_in; (void)out_size;

    const int threads = 256;
    const int blocks  = HBP / threads;   // 131072 / 256 = 512, exact
    cantor_attn_kernel<<<blocks, threads>>>(Qp, Kp, Vp, betas, temp, routes, out);
}